// round 15
// baseline (speedup 1.0000x reference)
#include <cuda_runtime.h>

typedef unsigned int u32;

#define BB 4
#define TT 2048
#define DD 1024
#define RR 32

// scratch (no allocations allowed)
__device__ float g_y[BB * TT * RR];      // y = x @ U (tf32-rounded)
__device__ float g_n[BB * TT];           // ||y||^2
__device__ float g_p[(size_t)BB * TT * TT];   // unnormalized probs (tf32-rounded)
__device__ float g_lp[BB * TT * 16];     // per-jtile row-sum partials
__device__ int   g_flag[BB * 32 * 64];   // [b][mtile(64 rows)][ktile(32 keys)]

__device__ __forceinline__ u32 s2u(const void* p) {
    u32 a;
    asm("{ .reg .u64 t; cvta.to.shared.u64 t, %1; cvt.u32.u64 %0, t; }" : "=r"(a) : "l"(p));
    return a;
}
__device__ __forceinline__ void cp16(u32 dst, const void* src) {
    asm volatile("cp.async.cg.shared.global [%0], [%1], 16;" :: "r"(dst), "l"(src));
}
__device__ __forceinline__ u32 fu(float v) { return __float_as_uint(v); }
__device__ __forceinline__ float tf32f(float v) {
    u32 r;
    asm("cvt.rna.tf32.f32 %0, %1;" : "=r"(r) : "f"(v));
    return __uint_as_float(r);
}
__device__ __forceinline__ u32 tf32u(float v) {
    u32 r;
    asm("cvt.rna.tf32.f32 %0, %1;" : "=r"(r) : "f"(v));
    return r;
}

__device__ __forceinline__ void mma8(float* d, const u32* a, u32 b0, u32 b1,
                                     const float* c) {
    asm volatile(
        "mma.sync.aligned.m16n8k8.row.col.f32.tf32.tf32.f32 "
        "{%0,%1,%2,%3}, {%4,%5,%6,%7}, {%8,%9}, {%10,%11,%12,%13};"
        : "=f"(d[0]), "=f"(d[1]), "=f"(d[2]), "=f"(d[3])
        : "r"(a[0]), "r"(a[1]), "r"(a[2]), "r"(a[3]), "r"(b0), "r"(b1),
          "f"(c[0]), "f"(c[1]), "f"(c[2]), "f"(c[3]));
}

// ---------------------------------------------------------------------------
// Kernel 1 (yn): y = x @ U via tensor cores, n = rowsum(y*y).
// CTA: 32 rows, 128 threads = 2m x 2n warps. Grid 256.
// 4-stage cp.async pipeline (3 chunks in flight), k-chunks of 64.
// ---------------------------------------------------------------------------
#define NST 4
#define YXS(st) ((st) * 2176)                    // [32][68] floats x4
#define YUS(st) (NST * 2176 + (st) * 2560)       // [64][40] floats x4
#define YN_NRED YXS(0)                           // epilogue reuse: [32][2]
#define YN_SMEM ((NST * 2176 + NST * 2560) * 4)  // 75776 B

__device__ __forceinline__ void yn_load_chunk(u32 su, const float* x, const float* U,
                                              int row0, int c, int tid) {
    const int st = c & (NST - 1);
    const int k0 = c * 64;
    for (int idx = tid; idx < 512; idx += 128) {
        int r_ = idx >> 4, u = idx & 15;
        cp16(su + (YXS(st) + r_ * 68 + u * 4) * 4,
             x + (size_t)(row0 + r_) * DD + k0 + u * 4);
    }
    for (int idx = tid; idx < 512; idx += 128) {
        int k = idx >> 3, u = idx & 7;
        cp16(su + (YUS(st) + k * 40 + u * 4) * 4,
             U + (size_t)(k0 + k) * RR + u * 4);
    }
}

__global__ __launch_bounds__(128, 2) void yn_kernel(const float* __restrict__ x,
                                                    const float* __restrict__ U) {
    extern __shared__ float s[];
    const u32 su = s2u(s);

    const int tid  = threadIdx.x;
    const int w    = tid >> 5;
    const int lane = tid & 31;
    const int wr   = w & 1;         // m half (16 rows)
    const int wc   = w >> 1;        // n half (16 cols)
    const int lq   = lane >> 2;
    const int lr   = lane & 3;
    const int row0 = blockIdx.x * 32;

    // prologue: chunks 0..2 in flight (3 groups)
#pragma unroll
    for (int c = 0; c < NST - 1; c++) {
        yn_load_chunk(su, x, U, row0, c, tid);
        asm volatile("cp.async.commit_group;" ::: "memory");
    }

    float acc[2][4];
#pragma unroll
    for (int nt = 0; nt < 2; nt++)
#pragma unroll
        for (int c = 0; c < 4; c++) acc[nt][c] = 0.f;

    for (int c = 0; c < 16; c++) {
        const int st = c & (NST - 1);
        asm volatile("cp.async.wait_group %0;" :: "n"(NST - 2) : "memory");
        __syncthreads();

        // issue chunk c+3 (or an empty group to keep the pending count fixed)
        if (c + NST - 1 < 16)
            yn_load_chunk(su, x, U, row0, c + NST - 1, tid);
        asm volatile("cp.async.commit_group;" ::: "memory");

        const float* sX = s + YXS(st);
        const float* sU = s + YUS(st);
#pragma unroll
        for (int kt = 0; kt < 8; kt++) {
            u32 a[4];
            const int ab = (wr * 16 + lq) * 68 + kt * 8 + lr;
            a[0] = fu(sX[ab]);
            a[1] = fu(sX[ab + 8 * 68]);
            a[2] = fu(sX[ab + 4]);
            a[3] = fu(sX[ab + 8 * 68 + 4]);
#pragma unroll
            for (int nt = 0; nt < 2; nt++) {
                u32 b0 = fu(sU[(kt * 8 + lr) * 40 + wc * 16 + nt * 8 + lq]);
                u32 b1 = fu(sU[(kt * 8 + lr + 4) * 40 + wc * 16 + nt * 8 + lq]);
                mma8(acc[nt], a, b0, b1, acc[nt]);
            }
        }
    }

    // epilogue: round, store y; n combine across the 2 wc warps
    const int r0g = row0 + wr * 16 + lq;
    const int r1g = r0g + 8;
    float n0 = 0.f, n1 = 0.f;
#pragma unroll
    for (int nt = 0; nt < 2; nt++) {
        float p0 = tf32f(acc[nt][0]), p1 = tf32f(acc[nt][1]);
        float p2 = tf32f(acc[nt][2]), p3 = tf32f(acc[nt][3]);
        *(float2*)&g_y[(size_t)r0g * RR + wc * 16 + nt * 8 + lr * 2] = make_float2(p0, p1);
        *(float2*)&g_y[(size_t)r1g * RR + wc * 16 + nt * 8 + lr * 2] = make_float2(p2, p3);
        n0 += p0 * p0 + p1 * p1;
        n1 += p2 * p2 + p3 * p3;
    }
    n0 += __shfl_xor_sync(0xffffffffu, n0, 1);
    n0 += __shfl_xor_sync(0xffffffffu, n0, 2);
    n1 += __shfl_xor_sync(0xffffffffu, n1, 1);
    n1 += __shfl_xor_sync(0xffffffffu, n1, 2);
    __syncthreads();   // all compute done before reusing YXS(0)
    if (lr == 0) {
        s[YN_NRED + (wr * 16 + lq) * 2 + wc]     = n0;
        s[YN_NRED + (wr * 16 + lq + 8) * 2 + wc] = n1;
    }
    __syncthreads();
    if (tid < 32)
        g_n[row0 + tid] = s[YN_NRED + tid * 2] + s[YN_NRED + tid * 2 + 1];
}

// ---------------------------------------------------------------------------
// Kernel 2 (pk): P̂ = exp(2 Yi.Yj^T - ni - nj) + row partials + flags.
// CTA 128i x 128j; 8 warps = 4 wm x 2 wn. Stores ONLY flagged 64x32 tiles.
// ---------------------------------------------------------------------------
#define PK_YI 0        // [128][36]
#define PK_YJ 4608     // [128][36]
#define PK_NJ 9216     // [128]
#define PK_FL 9344     // 8 ints
#define PK_SL 9352     // [2][128]
#define PK_SMEM ((9352 + 256) * 4)
#define YSTR 36

__global__ __launch_bounds__(256, 2) void pk_kernel() {
    extern __shared__ float s[];
    const u32 su = s2u(s);
    int* sflag = (int*)s + PK_FL;

    const int tid  = threadIdx.x;
    const int w    = tid >> 5;
    const int lane = tid & 31;
    const int wm   = w >> 1;        // 0..3
    const int wn   = w & 1;         // 0..1
    const int lq   = lane >> 2;
    const int lr   = lane & 3;

    const int b   = blockIdx.z;
    const int i0  = blockIdx.y * 128;
    const int j0  = blockIdx.x * 128;
    const int bTT = b * TT;

    for (int idx = tid; idx < 1024; idx += 256) {
        int r_ = idx >> 3, u = idx & 7;
        cp16(su + (PK_YI + r_ * YSTR) * 4 + u * 16,
             g_y + (size_t)(bTT + i0 + r_) * RR + u * 4);
        cp16(su + (PK_YJ + r_ * YSTR) * 4 + u * 16,
             g_y + (size_t)(bTT + j0 + r_) * RR + u * 4);
    }
    if (tid < 32) cp16(su + PK_NJ * 4 + tid * 16, g_n + bTT + j0 + tid * 4);
    if (tid < 8) sflag[tid] = 0;
    asm volatile("cp.async.commit_group;" ::: "memory");
    asm volatile("cp.async.wait_group 0;" ::: "memory");
    __syncthreads();

    float ni[2][2];
#pragma unroll
    for (int mt = 0; mt < 2; mt++) {
        ni[mt][0] = g_n[bTT + i0 + wm * 32 + mt * 16 + lq];
        ni[mt][1] = g_n[bTT + i0 + wm * 32 + mt * 16 + lq + 8];
    }

    float S[2][8][4];
#pragma unroll
    for (int mt = 0; mt < 2; mt++)
#pragma unroll
        for (int nt = 0; nt < 8; nt++)
#pragma unroll
            for (int c = 0; c < 4; c++) S[mt][nt][c] = 0.f;

#pragma unroll
    for (int kt = 0; kt < 4; kt++) {
        u32 aY[2][4];
#pragma unroll
        for (int mt = 0; mt < 2; mt++) {
            const int yib = PK_YI + (wm * 32 + mt * 16 + lq) * YSTR + kt * 8 + lr;
            aY[mt][0] = fu(s[yib]);
            aY[mt][1] = fu(s[yib + 8 * YSTR]);
            aY[mt][2] = fu(s[yib + 4]);
            aY[mt][3] = fu(s[yib + 8 * YSTR + 4]);
        }
#pragma unroll
        for (int nt = 0; nt < 8; nt++) {
            const int yjb = PK_YJ + (wn * 64 + nt * 8 + lq) * YSTR + kt * 8 + lr;
            u32 b0 = fu(s[yjb]);
            u32 b1 = fu(s[yjb + 4]);
            mma8(S[0][nt], aY[0], b0, b1, S[0][nt]);
            mma8(S[1][nt], aY[1], b0, b1, S[1][nt]);
        }
    }

    // ---- arg = 2S - ni - nj (in place) ----
#pragma unroll
    for (int mt = 0; mt < 2; mt++) {
#pragma unroll
        for (int nt = 0; nt < 8; nt++) {
            const float2 nj = *(const float2*)&s[PK_NJ + wn * 64 + nt * 8 + lr * 2];
            S[mt][nt][0] = fmaf(S[mt][nt][0], 2.f, -ni[mt][0] - nj.x);
            S[mt][nt][1] = fmaf(S[mt][nt][1], 2.f, -ni[mt][0] - nj.y);
            S[mt][nt][2] = fmaf(S[mt][nt][2], 2.f, -ni[mt][1] - nj.x);
            S[mt][nt][3] = fmaf(S[mt][nt][3], 2.f, -ni[mt][1] - nj.y);
        }
    }

    // ---- per (mt, 32-col group) exact max -> activity + tile flags ----
    bool act[2][2];
#pragma unroll
    for (int mt = 0; mt < 2; mt++) {
#pragma unroll
        for (int G = 0; G < 2; G++) {
            float m_ = -1e30f;
#pragma unroll
            for (int nt = G * 4; nt < G * 4 + 4; nt++)
#pragma unroll
                for (int c = 0; c < 4; c++) m_ = fmaxf(m_, S[mt][nt][c]);
#pragma unroll
            for (int off = 16; off; off >>= 1)
                m_ = fmaxf(m_, __shfl_xor_sync(0xffffffffu, m_, off));
            act[mt][G] = (m_ > -25.0f);
            if (act[mt][G] && lane == 0)
                sflag[(wm >> 1) * 4 + wn * 2 + G] = 1;
        }
    }
    __syncthreads();   // sflag complete (OR across warps)

    // ---- exp + store ONLY for flagged 64x32 tiles ----
    float lsum[2][2] = {{0.f, 0.f}, {0.f, 0.f}};
#pragma unroll
    for (int mt = 0; mt < 2; mt++) {
#pragma unroll
        for (int G = 0; G < 2; G++) {
            if (sflag[(wm >> 1) * 4 + wn * 2 + G]) {
                if (act[mt][G]) {
#pragma unroll
                    for (int nt = G * 4; nt < G * 4 + 4; nt++) {
                        float p0 = tf32f(__expf(S[mt][nt][0]));
                        float p1 = tf32f(__expf(S[mt][nt][1]));
                        float p2 = tf32f(__expf(S[mt][nt][2]));
                        float p3 = tf32f(__expf(S[mt][nt][3]));
                        lsum[mt][0] += p0 + p1;
                        lsum[mt][1] += p2 + p3;
                        const size_t r0 = (size_t)(bTT + i0 + wm * 32 + mt * 16 + lq) * TT
                                          + j0 + wn * 64 + nt * 8 + lr * 2;
                        *(float2*)&g_p[r0]          = make_float2(p0, p1);
                        *(float2*)&g_p[r0 + 8 * TT] = make_float2(p2, p3);
                    }
                } else {
#pragma unroll
                    for (int nt = G * 4; nt < G * 4 + 4; nt++) {
                        const size_t r0 = (size_t)(bTT + i0 + wm * 32 + mt * 16 + lq) * TT
                                          + j0 + wn * 64 + nt * 8 + lr * 2;
                        *(float2*)&g_p[r0]          = make_float2(0.f, 0.f);
                        *(float2*)&g_p[r0 + 8 * TT] = make_float2(0.f, 0.f);
                    }
                }
            }
        }
    }

    // ---- row partials + flags out ----
#pragma unroll
    for (int mt = 0; mt < 2; mt++)
#pragma unroll
        for (int h = 0; h < 2; h++) {
            float v = lsum[mt][h];
            v += __shfl_xor_sync(0xffffffffu, v, 1);
            v += __shfl_xor_sync(0xffffffffu, v, 2);
            if (lr == 0)
                s[PK_SL + wn * 128 + wm * 32 + mt * 16 + lq + 8 * h] = v;
        }
    __syncthreads();
    if (tid < 128) {
        g_lp[(size_t)(bTT + i0 + tid) * 16 + blockIdx.x] =
            s[PK_SL + tid] + s[PK_SL + 128 + tid];
    }
    if (tid < 8) {
        const int mtile = (i0 >> 6) + (tid >> 2);
        const int kt    = (j0 >> 5) + (tid & 3);
        g_flag[(b * 32 + mtile) * 64 + kt] = sflag[tid];
    }
}

// ---------------------------------------------------------------------------
// Kernel 3 (gemm2): out = (P̂ @ rna(x)) / l, visiting only flagged k-tiles.
// CTA = 64m x 256n; 8 warps = 2 wm x 4 wn; warp 32m x 64n; 2 CTAs/SM.
// ---------------------------------------------------------------------------
#define A_F(q) ((q) * 2304)             // [64][36] x2
#define X_F(q) (4608 + (q) * 8448)      // [32][264] x2
#define G2_SMEM ((4608 + 2 * 8448) * 4) // 86016 B
#define XSTR 264

#define G2_LOAD(tt, qq) do {                                                   \
    for (int idx = tid; idx < 512; idx += 256) {                               \
        int r_ = idx >> 3, u = idx & 7;                                        \
        cp16(su + A_F(qq) * 4 + (r_ * YSTR + u * 4) * 4,                       \
             g_p + (size_t)(bTT + m0 + r_) * TT + (tt) * 32 + u * 4);          \
    }                                                                          \
    for (int idx = tid; idx < 2048; idx += 256) {                              \
        int r_ = idx >> 6, u = idx & 63;                                       \
        cp16(su + X_F(qq) * 4 + (r_ * XSTR + u * 4) * 4,                       \
             x + (size_t)(bTT + (tt) * 32 + r_) * DD + dc0 + u * 4);           \
    }                                                                          \
    asm volatile("cp.async.commit_group;" ::: "memory");                       \
} while (0)

__global__ __launch_bounds__(256, 2) void gemm2_kernel(const float* __restrict__ x,
                                                       float* __restrict__ out) {
    extern __shared__ float s[];
    const u32 su = s2u(s);

    const int tid  = threadIdx.x;
    const int w    = tid >> 5;
    const int lane = tid & 31;
    const int wm   = w >> 2;        // 0..1
    const int wn   = w & 3;         // 0..3
    const int lq   = lane >> 2;
    const int lr   = lane & 3;

    const int b   = blockIdx.z;
    const int m0  = blockIdx.y * 64;
    const int dc0 = blockIdx.x * 256;
    const int bTT = b * TT;

    const int* fb = &g_flag[(b * 32 + (m0 >> 6)) * 64];

    float acc[2][8][4];
#pragma unroll
    for (int mt = 0; mt < 2; mt++)
#pragma unroll
        for (int nt = 0; nt < 8; nt++)
#pragma unroll
            for (int c = 0; c < 4; c++) acc[mt][nt][c] = 0.f;

    int t = 0;
    while (t < 64 && fb[t] == 0) t++;
    int q = 0;
    if (t < 64) G2_LOAD(t, 0);

    while (t < 64) {
        int tn = t + 1;
        while (tn < 64 && fb[tn] == 0) tn++;

        asm volatile("cp.async.wait_group 0;" ::: "memory");
        __syncthreads();

        if (tn < 64) G2_LOAD(tn, 1 - q);

        // A fragments (P rows)
        u32 aP[2][4][4];
#pragma unroll
        for (int mt = 0; mt < 2; mt++) {
            const int pab = A_F(q) + (wm * 32 + mt * 16 + lq) * YSTR + lr;
#pragma unroll
            for (int kt = 0; kt < 4; kt++) {
                aP[mt][kt][0] = fu(s[pab + kt * 8]);
                aP[mt][kt][1] = fu(s[pab + kt * 8 + 8 * YSTR]);
                aP[mt][kt][2] = fu(s[pab + kt * 8 + 4]);
                aP[mt][kt][3] = fu(s[pab + kt * 8 + 8 * YSTR + 4]);
            }
        }
        const int xb = X_F(q) + lr * XSTR + wn * 64 + lq;
#pragma unroll
        for (int nt = 0; nt < 8; nt++) {
#pragma unroll
            for (int kt = 0; kt < 4; kt++) {
                u32 b0 = tf32u(s[xb + kt * 8 * XSTR + nt * 8]);
                u32 b1 = tf32u(s[xb + (kt * 8 + 4) * XSTR + nt * 8]);
                mma8(acc[0][nt], aP[0][kt], b0, b1, acc[0][nt]);
                mma8(acc[1][nt], aP[1][kt], b0, b1, acc[1][nt]);
            }
        }

        q ^= 1;
        t = tn;
    }

    // ---- epilogue: normalize by l = sum of 16 partials, store ----
#pragma unroll
    for (int mt = 0; mt < 2; mt++) {
#pragma unroll
        for (int h = 0; h < 2; h++) {
            const int row = wm * 32 + mt * 16 + lq + 8 * h;
            const float* lp = &g_lp[(size_t)(bTT + m0 + row) * 16];
            const float4 a0 = *(const float4*)(lp + 0);
            const float4 a1 = *(const float4*)(lp + 4);
            const float4 a2 = *(const float4*)(lp + 8);
            const float4 a3 = *(const float4*)(lp + 12);
            const float l = ((a0.x + a0.y) + (a0.z + a0.w)) +
                            ((a1.x + a1.y) + (a1.z + a1.w)) +
                            ((a2.x + a2.y) + (a2.z + a2.w)) +
                            ((a3.x + a3.y) + (a3.z + a3.w));
            const float inv = 1.0f / l;
            float* o = out + (size_t)(bTT + m0 + row) * DD + dc0 + wn * 64 + lr * 2;
#pragma unroll
            for (int nt = 0; nt < 8; nt++) {
                *(float2*)(o + nt * 8) = make_float2(acc[mt][nt][2 * h] * inv,
                                                     acc[mt][nt][2 * h + 1] * inv);
            }
        }
    }
}

extern "C" void kernel_launch(void* const* d_in, const int* in_sizes, int n_in,
                              void* d_out, int out_size) {
    const float* x = (const float*)d_in[0];   // [B,T,D] fp32
    const float* U = (const float*)d_in[1];   // [D,R]   fp32
    float* out = (float*)d_out;

    cudaFuncSetAttribute(yn_kernel, cudaFuncAttributeMaxDynamicSharedMemorySize,
                         YN_SMEM);
    yn_kernel<<<(BB * TT) / 32, 128, YN_SMEM>>>(x, U);

    dim3 gpk(TT / 128, TT / 128, BB);
    pk_kernel<<<gpk, 256, PK_SMEM>>>();

    cudaFuncSetAttribute(gemm2_kernel, cudaFuncAttributeMaxDynamicSharedMemorySize,
                         G2_SMEM);
    dim3 g2(DD / 256, TT / 64, BB);
    gemm2_kernel<<<g2, 256, G2_SMEM>>>(x, out);
}

// round 16
// speedup vs baseline: 1.4416x; 1.4416x over previous
#include <cuda_runtime.h>

typedef unsigned int u32;

#define BB 4
#define TT 2048
#define DD 1024
#define RR 32

// scratch (no allocations allowed)
__device__ float g_y[BB * TT * RR];      // y = x @ U (tf32-rounded)
__device__ float g_n[BB * TT];           // ||y||^2
__device__ float g_p[(size_t)BB * TT * TT];   // unnormalized probs (tf32-rounded)
__device__ float g_lp[BB * TT * 16];     // per-jtile row-sum partials
__device__ int   g_flag[BB * 32 * 64];   // [b][mtile(64 rows)][ktile(32 keys)]

__device__ __forceinline__ u32 s2u(const void* p) {
    u32 a;
    asm("{ .reg .u64 t; cvta.to.shared.u64 t, %1; cvt.u32.u64 %0, t; }" : "=r"(a) : "l"(p));
    return a;
}
__device__ __forceinline__ void cp16(u32 dst, const void* src) {
    asm volatile("cp.async.cg.shared.global [%0], [%1], 16;" :: "r"(dst), "l"(src));
}
__device__ __forceinline__ u32 fu(float v) { return __float_as_uint(v); }
__device__ __forceinline__ float tf32f(float v) {
    u32 r;
    asm("cvt.rna.tf32.f32 %0, %1;" : "=r"(r) : "f"(v));
    return __uint_as_float(r);
}
__device__ __forceinline__ u32 tf32u(float v) {
    u32 r;
    asm("cvt.rna.tf32.f32 %0, %1;" : "=r"(r) : "f"(v));
    return r;
}

__device__ __forceinline__ void mma8(float* d, const u32* a, u32 b0, u32 b1,
                                     const float* c) {
    asm volatile(
        "mma.sync.aligned.m16n8k8.row.col.f32.tf32.tf32.f32 "
        "{%0,%1,%2,%3}, {%4,%5,%6,%7}, {%8,%9}, {%10,%11,%12,%13};"
        : "=f"(d[0]), "=f"(d[1]), "=f"(d[2]), "=f"(d[3])
        : "r"(a[0]), "r"(a[1]), "r"(a[2]), "r"(a[3]), "r"(b0), "r"(b1),
          "f"(c[0]), "f"(c[1]), "f"(c[2]), "f"(c[3]));
}

// ---------------------------------------------------------------------------
// Kernel 1 (yn): y = x @ U via tensor cores, n = rowsum(y*y).
// CTA: 32 rows, 128 threads = 2m x 2n warps (warp tile 16m x 16n).
// Grid 256; k-chunks of 64, double-buffered.  (R14 configuration)
// ---------------------------------------------------------------------------
#define YXS(q) ((q) * 2176)             // [32][68] floats
#define YUS(q) (4352 + (q) * 2560)      // [64][40] floats
#define YN_NRED YXS(0)                  // epilogue reuse: [32][2]
#define YN_SMEM ((4352 + 2 * 2560) * 4) // 37888 B

__global__ __launch_bounds__(128, 4) void yn_kernel(const float* __restrict__ x,
                                                    const float* __restrict__ U) {
    extern __shared__ float s[];
    const u32 su = s2u(s);

    const int tid  = threadIdx.x;
    const int w    = tid >> 5;
    const int lane = tid & 31;
    const int wr   = w & 1;         // m half (16 rows)
    const int wc   = w >> 1;        // n half (16 cols)
    const int lq   = lane >> 2;
    const int lr   = lane & 3;
    const int row0 = blockIdx.x * 32;

    // prologue: chunk 0
    for (int idx = tid; idx < 512; idx += 128) {
        int r_ = idx >> 4, u = idx & 15;
        cp16(su + (YXS(0) + r_ * 68 + u * 4) * 4,
             x + (size_t)(row0 + r_) * DD + u * 4);
    }
    for (int idx = tid; idx < 512; idx += 128) {
        int k = idx >> 3, u = idx & 7;
        cp16(su + (YUS(0) + k * 40 + u * 4) * 4, U + (size_t)k * RR + u * 4);
    }
    asm volatile("cp.async.commit_group;" ::: "memory");

    float acc[2][4];
#pragma unroll
    for (int nt = 0; nt < 2; nt++)
#pragma unroll
        for (int c = 0; c < 4; c++) acc[nt][c] = 0.f;

    for (int c = 0; c < 16; c++) {
        const int q = c & 1;
        asm volatile("cp.async.wait_group 0;" ::: "memory");
        __syncthreads();

        if (c + 1 < 16) {
            const int k0 = (c + 1) * 64;
            for (int idx = tid; idx < 512; idx += 128) {
                int r_ = idx >> 4, u = idx & 15;
                cp16(su + (YXS(1 - q) + r_ * 68 + u * 4) * 4,
                     x + (size_t)(row0 + r_) * DD + k0 + u * 4);
            }
            for (int idx = tid; idx < 512; idx += 128) {
                int k = idx >> 3, u = idx & 7;
                cp16(su + (YUS(1 - q) + k * 40 + u * 4) * 4,
                     U + (size_t)(k0 + k) * RR + u * 4);
            }
            asm volatile("cp.async.commit_group;" ::: "memory");
        }

        const float* sX = s + YXS(q);
        const float* sU = s + YUS(q);
#pragma unroll
        for (int kt = 0; kt < 8; kt++) {
            u32 a[4];
            const int ab = (wr * 16 + lq) * 68 + kt * 8 + lr;
            a[0] = fu(sX[ab]);
            a[1] = fu(sX[ab + 8 * 68]);
            a[2] = fu(sX[ab + 4]);
            a[3] = fu(sX[ab + 8 * 68 + 4]);
#pragma unroll
            for (int nt = 0; nt < 2; nt++) {
                u32 b0 = fu(sU[(kt * 8 + lr) * 40 + wc * 16 + nt * 8 + lq]);
                u32 b1 = fu(sU[(kt * 8 + lr + 4) * 40 + wc * 16 + nt * 8 + lq]);
                mma8(acc[nt], a, b0, b1, acc[nt]);
            }
        }
    }

    // epilogue: round, store y; n combine across the 2 wc warps
    const int r0g = row0 + wr * 16 + lq;
    const int r1g = r0g + 8;
    float n0 = 0.f, n1 = 0.f;
#pragma unroll
    for (int nt = 0; nt < 2; nt++) {
        float p0 = tf32f(acc[nt][0]), p1 = tf32f(acc[nt][1]);
        float p2 = tf32f(acc[nt][2]), p3 = tf32f(acc[nt][3]);
        *(float2*)&g_y[(size_t)r0g * RR + wc * 16 + nt * 8 + lr * 2] = make_float2(p0, p1);
        *(float2*)&g_y[(size_t)r1g * RR + wc * 16 + nt * 8 + lr * 2] = make_float2(p2, p3);
        n0 += p0 * p0 + p1 * p1;
        n1 += p2 * p2 + p3 * p3;
    }
    n0 += __shfl_xor_sync(0xffffffffu, n0, 1);
    n0 += __shfl_xor_sync(0xffffffffu, n0, 2);
    n1 += __shfl_xor_sync(0xffffffffu, n1, 1);
    n1 += __shfl_xor_sync(0xffffffffu, n1, 2);
    __syncthreads();   // all compute done before reusing YXS(0)
    if (lr == 0) {
        s[YN_NRED + (wr * 16 + lq) * 2 + wc]     = n0;
        s[YN_NRED + (wr * 16 + lq + 8) * 2 + wc] = n1;
    }
    __syncthreads();
    if (tid < 32)
        g_n[row0 + tid] = s[YN_NRED + tid * 2] + s[YN_NRED + tid * 2 + 1];
}

// ---------------------------------------------------------------------------
// Kernel 2 (pk): P̂ = exp(2 Yi.Yj^T - ni - nj) + row partials + flags.
// CTA 128i x 128j; 8 warps = 4 wm x 2 wn. Stores ONLY flagged 64x32 tiles.
// ---------------------------------------------------------------------------
#define PK_YI 0        // [128][36]
#define PK_YJ 4608     // [128][36]
#define PK_NJ 9216     // [128]
#define PK_FL 9344     // 8 ints
#define PK_SL 9352     // [2][128]
#define PK_SMEM ((9352 + 256) * 4)
#define YSTR 36

__global__ __launch_bounds__(256, 2) void pk_kernel() {
    extern __shared__ float s[];
    const u32 su = s2u(s);
    int* sflag = (int*)s + PK_FL;

    const int tid  = threadIdx.x;
    const int w    = tid >> 5;
    const int lane = tid & 31;
    const int wm   = w >> 1;        // 0..3
    const int wn   = w & 1;         // 0..1
    const int lq   = lane >> 2;
    const int lr   = lane & 3;

    const int b   = blockIdx.z;
    const int i0  = blockIdx.y * 128;
    const int j0  = blockIdx.x * 128;
    const int bTT = b * TT;

    for (int idx = tid; idx < 1024; idx += 256) {
        int r_ = idx >> 3, u = idx & 7;
        cp16(su + (PK_YI + r_ * YSTR) * 4 + u * 16,
             g_y + (size_t)(bTT + i0 + r_) * RR + u * 4);
        cp16(su + (PK_YJ + r_ * YSTR) * 4 + u * 16,
             g_y + (size_t)(bTT + j0 + r_) * RR + u * 4);
    }
    if (tid < 32) cp16(su + PK_NJ * 4 + tid * 16, g_n + bTT + j0 + tid * 4);
    if (tid < 8) sflag[tid] = 0;
    asm volatile("cp.async.commit_group;" ::: "memory");
    asm volatile("cp.async.wait_group 0;" ::: "memory");
    __syncthreads();

    float ni[2][2];
#pragma unroll
    for (int mt = 0; mt < 2; mt++) {
        ni[mt][0] = g_n[bTT + i0 + wm * 32 + mt * 16 + lq];
        ni[mt][1] = g_n[bTT + i0 + wm * 32 + mt * 16 + lq + 8];
    }

    float S[2][8][4];
#pragma unroll
    for (int mt = 0; mt < 2; mt++)
#pragma unroll
        for (int nt = 0; nt < 8; nt++)
#pragma unroll
            for (int c = 0; c < 4; c++) S[mt][nt][c] = 0.f;

#pragma unroll
    for (int kt = 0; kt < 4; kt++) {
        u32 aY[2][4];
#pragma unroll
        for (int mt = 0; mt < 2; mt++) {
            const int yib = PK_YI + (wm * 32 + mt * 16 + lq) * YSTR + kt * 8 + lr;
            aY[mt][0] = fu(s[yib]);
            aY[mt][1] = fu(s[yib + 8 * YSTR]);
            aY[mt][2] = fu(s[yib + 4]);
            aY[mt][3] = fu(s[yib + 8 * YSTR + 4]);
        }
#pragma unroll
        for (int nt = 0; nt < 8; nt++) {
            const int yjb = PK_YJ + (wn * 64 + nt * 8 + lq) * YSTR + kt * 8 + lr;
            u32 b0 = fu(s[yjb]);
            u32 b1 = fu(s[yjb + 4]);
            mma8(S[0][nt], aY[0], b0, b1, S[0][nt]);
            mma8(S[1][nt], aY[1], b0, b1, S[1][nt]);
        }
    }

    // ---- arg = 2S - ni - nj (in place) ----
#pragma unroll
    for (int mt = 0; mt < 2; mt++) {
#pragma unroll
        for (int nt = 0; nt < 8; nt++) {
            const float2 nj = *(const float2*)&s[PK_NJ + wn * 64 + nt * 8 + lr * 2];
            S[mt][nt][0] = fmaf(S[mt][nt][0], 2.f, -ni[mt][0] - nj.x);
            S[mt][nt][1] = fmaf(S[mt][nt][1], 2.f, -ni[mt][0] - nj.y);
            S[mt][nt][2] = fmaf(S[mt][nt][2], 2.f, -ni[mt][1] - nj.x);
            S[mt][nt][3] = fmaf(S[mt][nt][3], 2.f, -ni[mt][1] - nj.y);
        }
    }

    // ---- per (mt, 32-col group) exact max -> activity + tile flags ----
    bool act[2][2];
#pragma unroll
    for (int mt = 0; mt < 2; mt++) {
#pragma unroll
        for (int G = 0; G < 2; G++) {
            float m_ = -1e30f;
#pragma unroll
            for (int nt = G * 4; nt < G * 4 + 4; nt++)
#pragma unroll
                for (int c = 0; c < 4; c++) m_ = fmaxf(m_, S[mt][nt][c]);
#pragma unroll
            for (int off = 16; off; off >>= 1)
                m_ = fmaxf(m_, __shfl_xor_sync(0xffffffffu, m_, off));
            act[mt][G] = (m_ > -25.0f);
            if (act[mt][G] && lane == 0)
                sflag[(wm >> 1) * 4 + wn * 2 + G] = 1;
        }
    }
    __syncthreads();   // sflag complete (OR across warps)

    // ---- exp + store ONLY for flagged 64x32 tiles ----
    float lsum[2][2] = {{0.f, 0.f}, {0.f, 0.f}};
#pragma unroll
    for (int mt = 0; mt < 2; mt++) {
#pragma unroll
        for (int G = 0; G < 2; G++) {
            if (sflag[(wm >> 1) * 4 + wn * 2 + G]) {
                if (act[mt][G]) {
#pragma unroll
                    for (int nt = G * 4; nt < G * 4 + 4; nt++) {
                        float p0 = tf32f(__expf(S[mt][nt][0]));
                        float p1 = tf32f(__expf(S[mt][nt][1]));
                        float p2 = tf32f(__expf(S[mt][nt][2]));
                        float p3 = tf32f(__expf(S[mt][nt][3]));
                        lsum[mt][0] += p0 + p1;
                        lsum[mt][1] += p2 + p3;
                        const size_t r0 = (size_t)(bTT + i0 + wm * 32 + mt * 16 + lq) * TT
                                          + j0 + wn * 64 + nt * 8 + lr * 2;
                        *(float2*)&g_p[r0]          = make_float2(p0, p1);
                        *(float2*)&g_p[r0 + 8 * TT] = make_float2(p2, p3);
                    }
                } else {
#pragma unroll
                    for (int nt = G * 4; nt < G * 4 + 4; nt++) {
                        const size_t r0 = (size_t)(bTT + i0 + wm * 32 + mt * 16 + lq) * TT
                                          + j0 + wn * 64 + nt * 8 + lr * 2;
                        *(float2*)&g_p[r0]          = make_float2(0.f, 0.f);
                        *(float2*)&g_p[r0 + 8 * TT] = make_float2(0.f, 0.f);
                    }
                }
            }
        }
    }

    // ---- row partials + flags out ----
#pragma unroll
    for (int mt = 0; mt < 2; mt++)
#pragma unroll
        for (int h = 0; h < 2; h++) {
            float v = lsum[mt][h];
            v += __shfl_xor_sync(0xffffffffu, v, 1);
            v += __shfl_xor_sync(0xffffffffu, v, 2);
            if (lr == 0)
                s[PK_SL + wn * 128 + wm * 32 + mt * 16 + lq + 8 * h] = v;
        }
    __syncthreads();
    if (tid < 128) {
        g_lp[(size_t)(bTT + i0 + tid) * 16 + blockIdx.x] =
            s[PK_SL + tid] + s[PK_SL + 128 + tid];
    }
    if (tid < 8) {
        const int mtile = (i0 >> 6) + (tid >> 2);
        const int kt    = (j0 >> 5) + (tid & 3);
        g_flag[(b * 32 + mtile) * 64 + kt] = sflag[tid];
    }
}

// ---------------------------------------------------------------------------
// Kernel 3 (gemm2): out = (P̂ @ rna(x)) / l, visiting only flagged k-tiles.
// CTA = 64m x 256n; 8 warps = 2 wm x 4 wn; warp 32m x 64n; 2 CTAs/SM.
// l-normalizers hoisted to kernel start (hide g_lp latency under mainloop).
// ---------------------------------------------------------------------------
#define A_F(q) ((q) * 2304)             // [64][36] x2
#define X_F(q) (4608 + (q) * 8448)      // [32][264] x2
#define G2_SMEM ((4608 + 2 * 8448) * 4) // 86016 B
#define XSTR 264

#define G2_LOAD(tt, qq) do {                                                   \
    for (int idx = tid; idx < 512; idx += 256) {                               \
        int r_ = idx >> 3, u = idx & 7;                                        \
        cp16(su + A_F(qq) * 4 + (r_ * YSTR + u * 4) * 4,                       \
             g_p + (size_t)(bTT + m0 + r_) * TT + (tt) * 32 + u * 4);          \
    }                                                                          \
    for (int idx = tid; idx < 2048; idx += 256) {                              \
        int r_ = idx >> 6, u = idx & 63;                                       \
        cp16(su + X_F(qq) * 4 + (r_ * XSTR + u * 4) * 4,                       \
             x + (size_t)(bTT + (tt) * 32 + r_) * DD + dc0 + u * 4);           \
    }                                                                          \
    asm volatile("cp.async.commit_group;" ::: "memory");                       \
} while (0)

__global__ __launch_bounds__(256, 2) void gemm2_kernel(const float* __restrict__ x,
                                                       float* __restrict__ out) {
    extern __shared__ float s[];
    const u32 su = s2u(s);

    const int tid  = threadIdx.x;
    const int w    = tid >> 5;
    const int lane = tid & 31;
    const int wm   = w >> 2;        // 0..1
    const int wn   = w & 3;         // 0..3
    const int lq   = lane >> 2;
    const int lr   = lane & 3;

    const int b   = blockIdx.z;
    const int m0  = blockIdx.y * 64;
    const int dc0 = blockIdx.x * 256;
    const int bTT = b * TT;

    const int* fb = &g_flag[(b * 32 + (m0 >> 6)) * 64];

    // ---- hoisted normalizers: inv[mt][h] computed before the mainloop ----
    float inv[2][2];
#pragma unroll
    for (int mt = 0; mt < 2; mt++) {
#pragma unroll
        for (int h = 0; h < 2; h++) {
            const int row = wm * 32 + mt * 16 + lq + 8 * h;
            const float* lp = &g_lp[(size_t)(bTT + m0 + row) * 16];
            const float4 a0 = *(const float4*)(lp + 0);
            const float4 a1 = *(const float4*)(lp + 4);
            const float4 a2 = *(const float4*)(lp + 8);
            const float4 a3 = *(const float4*)(lp + 12);
            const float l = ((a0.x + a0.y) + (a0.z + a0.w)) +
                            ((a1.x + a1.y) + (a1.z + a1.w)) +
                            ((a2.x + a2.y) + (a2.z + a2.w)) +
                            ((a3.x + a3.y) + (a3.z + a3.w));
            inv[mt][h] = 1.0f / l;
        }
    }

    float acc[2][8][4];
#pragma unroll
    for (int mt = 0; mt < 2; mt++)
#pragma unroll
        for (int nt = 0; nt < 8; nt++)
#pragma unroll
            for (int c = 0; c < 4; c++) acc[mt][nt][c] = 0.f;

    int t = 0;
    while (t < 64 && fb[t] == 0) t++;
    int q = 0;
    if (t < 64) G2_LOAD(t, 0);

    while (t < 64) {
        int tn = t + 1;
        while (tn < 64 && fb[tn] == 0) tn++;

        asm volatile("cp.async.wait_group 0;" ::: "memory");
        __syncthreads();

        if (tn < 64) G2_LOAD(tn, 1 - q);

        // A fragments (P rows)
        u32 aP[2][4][4];
#pragma unroll
        for (int mt = 0; mt < 2; mt++) {
            const int pab = A_F(q) + (wm * 32 + mt * 16 + lq) * YSTR + lr;
#pragma unroll
            for (int kt = 0; kt < 4; kt++) {
                aP[mt][kt][0] = fu(s[pab + kt * 8]);
                aP[mt][kt][1] = fu(s[pab + kt * 8 + 8 * YSTR]);
                aP[mt][kt][2] = fu(s[pab + kt * 8 + 4]);
                aP[mt][kt][3] = fu(s[pab + kt * 8 + 8 * YSTR + 4]);
            }
        }
        const int xb = X_F(q) + lr * XSTR + wn * 64 + lq;
#pragma unroll
        for (int nt = 0; nt < 8; nt++) {
#pragma unroll
            for (int kt = 0; kt < 4; kt++) {
                u32 b0 = tf32u(s[xb + kt * 8 * XSTR + nt * 8]);
                u32 b1 = tf32u(s[xb + (kt * 8 + 4) * XSTR + nt * 8]);
                mma8(acc[0][nt], aP[0][kt], b0, b1, acc[0][nt]);
                mma8(acc[1][nt], aP[1][kt], b0, b1, acc[1][nt]);
            }
        }

        q ^= 1;
        t = tn;
    }

    // ---- epilogue: normalize (registers) and store ----
#pragma unroll
    for (int mt = 0; mt < 2; mt++) {
#pragma unroll
        for (int h = 0; h < 2; h++) {
            const int row = wm * 32 + mt * 16 + lq + 8 * h;
            const float iv = inv[mt][h];
            float* o = out + (size_t)(bTT + m0 + row) * DD + dc0 + wn * 64 + lr * 2;
#pragma unroll
            for (int nt = 0; nt < 8; nt++) {
                *(float2*)(o + nt * 8) = make_float2(acc[mt][nt][2 * h] * iv,
                                                     acc[mt][nt][2 * h + 1] * iv);
            }
        }
    }
}

extern "C" void kernel_launch(void* const* d_in, const int* in_sizes, int n_in,
                              void* d_out, int out_size) {
    const float* x = (const float*)d_in[0];   // [B,T,D] fp32
    const float* U = (const float*)d_in[1];   // [D,R]   fp32
    float* out = (float*)d_out;

    cudaFuncSetAttribute(yn_kernel, cudaFuncAttributeMaxDynamicSharedMemorySize,
                         YN_SMEM);
    yn_kernel<<<(BB * TT) / 32, 128, YN_SMEM>>>(x, U);

    dim3 gpk(TT / 128, TT / 128, BB);
    pk_kernel<<<gpk, 256, PK_SMEM>>>();

    cudaFuncSetAttribute(gemm2_kernel, cudaFuncAttributeMaxDynamicSharedMemorySize,
                         G2_SMEM);
    dim3 g2(DD / 256, TT / 64, BB);
    gemm2_kernel<<<g2, 256, G2_SMEM>>>(x, out);
}